// round 1
// baseline (speedup 1.0000x reference)
#include <cuda_runtime.h>
#include <math.h>

#define BB 4
#define NN 4096
#define CC 256
#define CK 32

// Scratch (device globals — no allocation allowed)
__device__ float d_f[BB * NN * CK];
__device__ float d_g[BB * NN * CK];
__device__ float d_h[(size_t)BB * NN * CC];
__device__ float d_o[(size_t)BB * NN * CC];

typedef unsigned long long ull;

__device__ __forceinline__ ull pack2(float lo, float hi) {
    ull r; asm("mov.b64 %0, {%1, %2};" : "=l"(r) : "f"(lo), "f"(hi)); return r;
}
__device__ __forceinline__ void unpack2(ull v, float& lo, float& hi) {
    asm("mov.b64 {%0, %1}, %2;" : "=f"(lo), "=f"(hi) : "l"(v));
}
__device__ __forceinline__ ull ffma2(ull a, ull b, ull c) {
    ull d; asm("fma.rn.f32x2 %0, %1, %2, %3;" : "=l"(d) : "l"(a), "l"(b), "l"(c)); return d;
}
__device__ __forceinline__ ull fmul2(ull a, ull b) {
    ull d; asm("mul.rn.f32x2 %0, %1, %2;" : "=l"(d) : "l"(a), "l"(b)); return d;
}

// ---------------------------------------------------------------------------
// f/g projection: [16384,256] @ ([256,32]||[256,32]) -> d_f, d_g
// Block: 256 threads, 64 rows x 64 cols (f cols 0-31, g cols 32-63)
// ---------------------------------------------------------------------------
__global__ __launch_bounds__(256) void k_proj_fg(
    const float* __restrict__ x,
    const float* __restrict__ Wf, const float* __restrict__ bf,
    const float* __restrict__ Wg, const float* __restrict__ bg)
{
    __shared__ __align__(16) float sA[64 * 32];
    __shared__ __align__(16) float sW[32 * 64];
    const int tid = threadIdx.x;
    const int row0 = blockIdx.x * 64;
    const int ty = tid >> 4, tx = tid & 15;

    ull acc[4][2] = {};

    for (int k0 = 0; k0 < 256; k0 += 32) {
        __syncthreads();
#pragma unroll
        for (int i = 0; i < 2; i++) {
            int e4 = tid * 2 + i;
            int r = e4 >> 3, kk = (e4 & 7) << 2;
            *(float4*)&sA[r * 32 + kk] =
                *(const float4*)&x[(size_t)(row0 + r) * 256 + k0 + kk];
        }
#pragma unroll
        for (int i = 0; i < 8; i++) {
            int e = tid + 256 * i;
            int k = e >> 6, c = e & 63;
            float w = (c < 32) ? Wf[(k0 + k) * 32 + c] : Wg[(k0 + k) * 32 + (c - 32)];
            sW[k * 64 + c] = w;
        }
        __syncthreads();
#pragma unroll
        for (int k = 0; k < 32; ++k) {
            ulonglong2 wv = *(const ulonglong2*)&sW[k * 64 + tx * 4];
#pragma unroll
            for (int i = 0; i < 4; ++i) {
                float a = sA[(ty * 4 + i) * 32 + k];
                ull a2 = pack2(a, a);
                acc[i][0] = ffma2(a2, wv.x, acc[i][0]);
                acc[i][1] = ffma2(a2, wv.y, acc[i][1]);
            }
        }
    }

    const int cbase = tx * 4;
#pragma unroll
    for (int i = 0; i < 4; ++i) {
        float v0, v1, v2, v3;
        unpack2(acc[i][0], v0, v1);
        unpack2(acc[i][1], v2, v3);
        int row = row0 + ty * 4 + i;
        if (cbase < 32) {
            float4 o4 = make_float4(v0 + bf[cbase], v1 + bf[cbase + 1],
                                    v2 + bf[cbase + 2], v3 + bf[cbase + 3]);
            *(float4*)&d_f[row * CK + cbase] = o4;
        } else {
            int cg = cbase - 32;
            float4 o4 = make_float4(v0 + bg[cg], v1 + bg[cg + 1],
                                    v2 + bg[cg + 2], v3 + bg[cg + 3]);
            *(float4*)&d_g[row * CK + cg] = o4;
        }
    }
}

// ---------------------------------------------------------------------------
// Generic 256-col GEMM: out = A @ W + bias (+ res).  mode 0: A=x -> d_h.
// mode 1: A=d_o, res=x -> external out.
// ---------------------------------------------------------------------------
__global__ __launch_bounds__(256) void k_gemm256(
    const float* __restrict__ Aext, const float* __restrict__ W,
    const float* __restrict__ bias, const float* __restrict__ res,
    float* __restrict__ outext, int mode)
{
    const float* A = (mode == 0) ? Aext : d_o;
    float* out = (mode == 0) ? d_h : outext;

    __shared__ __align__(16) float sA[64 * 32];
    __shared__ __align__(16) float sW[32 * 64];
    const int tid = threadIdx.x;
    const int row0 = blockIdx.x * 64;
    const int n0 = blockIdx.y * 64;
    const int ty = tid >> 4, tx = tid & 15;

    ull acc[4][2] = {};

    for (int k0 = 0; k0 < 256; k0 += 32) {
        __syncthreads();
#pragma unroll
        for (int i = 0; i < 2; i++) {
            int e4 = tid * 2 + i;
            int r = e4 >> 3, kk = (e4 & 7) << 2;
            *(float4*)&sA[r * 32 + kk] =
                *(const float4*)&A[(size_t)(row0 + r) * 256 + k0 + kk];
        }
#pragma unroll
        for (int i = 0; i < 8; i++) {
            int e = tid + 256 * i;
            int k = e >> 6, c = e & 63;
            sW[k * 64 + c] = W[(size_t)(k0 + k) * 256 + n0 + c];
        }
        __syncthreads();
#pragma unroll
        for (int k = 0; k < 32; ++k) {
            ulonglong2 wv = *(const ulonglong2*)&sW[k * 64 + tx * 4];
#pragma unroll
            for (int i = 0; i < 4; ++i) {
                float a = sA[(ty * 4 + i) * 32 + k];
                ull a2 = pack2(a, a);
                acc[i][0] = ffma2(a2, wv.x, acc[i][0]);
                acc[i][1] = ffma2(a2, wv.y, acc[i][1]);
            }
        }
    }

    const int c0 = n0 + tx * 4;
    float4 b4 = *(const float4*)&bias[c0];
#pragma unroll
    for (int i = 0; i < 4; ++i) {
        float v0, v1, v2, v3;
        unpack2(acc[i][0], v0, v1);
        unpack2(acc[i][1], v2, v3);
        int row = row0 + ty * 4 + i;
        v0 += b4.x; v1 += b4.y; v2 += b4.z; v3 += b4.w;
        if (res) {
            float4 r4 = *(const float4*)&res[(size_t)row * 256 + c0];
            v0 += r4.x; v1 += r4.y; v2 += r4.z; v3 += r4.w;
        }
        *(float4*)&out[(size_t)row * 256 + c0] = make_float4(v0, v1, v2, v3);
    }
}

// ---------------------------------------------------------------------------
// Flash attention: per CTA: 64 query rows of one batch.
// s = g f^T (no scale), online softmax, o = beta @ h.
// smem: sg 8K + sfT 8K + sp 16K + sh 16K = 48KB (static, no attribute calls).
// ---------------------------------------------------------------------------
__global__ __launch_bounds__(256) void k_attn()
{
    __shared__ __align__(16) float sg[64 * 32];
    __shared__ __align__(16) float sfT[32 * 64];   // [k][key]
    __shared__ __align__(16) float sp[64 * 64];    // [q][key]
    __shared__ __align__(16) float sh[16 * 256];   // [key-chunk][c]

    const int tid = threadIdx.x;
    const int ty = tid >> 4, tx = tid & 15;
    const int b = blockIdx.y;
    const int q0 = blockIdx.x * 64;

    const float* fptr = d_f + (size_t)b * NN * CK;
    const float* gptr = d_g + (size_t)b * NN * CK;
    const float* hptr = d_h + (size_t)b * NN * CC;

    // load g tile (resident for whole kernel)
#pragma unroll
    for (int i = 0; i < 2; i++) {
        int e4 = tid * 2 + i;
        int r = e4 >> 3, kk = (e4 & 7) << 2;
        *(float4*)&sg[r * 32 + kk] = *(const float4*)&gptr[(q0 + r) * CK + kk];
    }

    const float NEG_INF = __int_as_float(0xff800000);
    float m_i[4] = {NEG_INF, NEG_INF, NEG_INF, NEG_INF};
    float l_i[4] = {0.f, 0.f, 0.f, 0.f};
    ull o2[4][8] = {};

    for (int kt = 0; kt < 64; ++kt) {
        const int k0 = kt * 64;
        __syncthreads();  // prior tile's sfT/sp reads complete
        // load f tile transposed: sfT[k][key] = f[k0+key][k]
#pragma unroll
        for (int i = 0; i < 2; i++) {
            int e4 = tid * 2 + i;
            int r = e4 >> 3, kk = (e4 & 7) << 2;
            float4 v = *(const float4*)&fptr[(k0 + r) * CK + kk];
            sfT[(kk + 0) * 64 + r] = v.x;
            sfT[(kk + 1) * 64 + r] = v.y;
            sfT[(kk + 2) * 64 + r] = v.z;
            sfT[(kk + 3) * 64 + r] = v.w;
        }
        __syncthreads();

        // s tile: 4 q-rows x 4 key-cols per thread
        ull ss2[4][2] = {};
#pragma unroll
        for (int k = 0; k < 32; ++k) {
            ulonglong2 wv = *(const ulonglong2*)&sfT[k * 64 + tx * 4];
#pragma unroll
            for (int i = 0; i < 4; ++i) {
                float a = sg[(ty * 4 + i) * 32 + k];
                ull a2 = pack2(a, a);
                ss2[i][0] = ffma2(a2, wv.x, ss2[i][0]);
                ss2[i][1] = ffma2(a2, wv.y, ss2[i][1]);
            }
        }

        // online softmax update per q-row (row spread across 16-lane tx group)
#pragma unroll
        for (int i = 0; i < 4; ++i) {
            float s0, s1, s2v, s3;
            unpack2(ss2[i][0], s0, s1);
            unpack2(ss2[i][1], s2v, s3);
            float mt = fmaxf(fmaxf(s0, s1), fmaxf(s2v, s3));
#pragma unroll
            for (int off = 8; off; off >>= 1)
                mt = fmaxf(mt, __shfl_xor_sync(0xffffffffu, mt, off));
            float mnew = fmaxf(m_i[i], mt);
            float p0 = __expf(s0 - mnew);
            float p1 = __expf(s1 - mnew);
            float p2v = __expf(s2v - mnew);
            float p3 = __expf(s3 - mnew);
            float ls = (p0 + p1) + (p2v + p3);
#pragma unroll
            for (int off = 8; off; off >>= 1)
                ls += __shfl_xor_sync(0xffffffffu, ls, off);
            float alpha = __expf(m_i[i] - mnew);
            l_i[i] = l_i[i] * alpha + ls;
            m_i[i] = mnew;
            ull a2 = pack2(alpha, alpha);
#pragma unroll
            for (int j = 0; j < 8; ++j) o2[i][j] = fmul2(o2[i][j], a2);
            *(float4*)&sp[(ty * 4 + i) * 64 + tx * 4] = make_float4(p0, p1, p2v, p3);
        }

        // o += p @ h, streaming h in 16-row chunks through smem
        for (int hc = 0; hc < 4; ++hc) {
            __syncthreads();  // sp visible (hc==0) / prior sh reads complete
#pragma unroll
            for (int i = 0; i < 4; ++i) {
                int e4 = tid + 256 * i;
                int r = e4 >> 6, c4 = (e4 & 63) << 2;
                *(float4*)&sh[r * 256 + c4] =
                    *(const float4*)&hptr[(size_t)(k0 + hc * 16 + r) * CC + c4];
            }
            __syncthreads();
#pragma unroll
            for (int kk = 0; kk < 16; ++kk) {
                ull p2[4];
#pragma unroll
                for (int i = 0; i < 4; ++i) {
                    float pv = sp[(ty * 4 + i) * 64 + hc * 16 + kk];
                    p2[i] = pack2(pv, pv);
                }
#pragma unroll
                for (int j = 0; j < 4; ++j) {
                    ulonglong2 hv = *(const ulonglong2*)&sh[kk * 256 + j * 64 + tx * 4];
#pragma unroll
                    for (int i = 0; i < 4; ++i) {
                        o2[i][2 * j]     = ffma2(p2[i], hv.x, o2[i][2 * j]);
                        o2[i][2 * j + 1] = ffma2(p2[i], hv.y, o2[i][2 * j + 1]);
                    }
                }
            }
        }
    }

    // epilogue: o / l -> d_o
    float* optr = d_o + (size_t)b * NN * CC;
#pragma unroll
    for (int i = 0; i < 4; ++i) {
        float inv = 1.0f / l_i[i];
        int row = q0 + ty * 4 + i;
#pragma unroll
        for (int j = 0; j < 4; ++j) {
            float a, bb2, c, d;
            unpack2(o2[i][2 * j], a, bb2);
            unpack2(o2[i][2 * j + 1], c, d);
            *(float4*)&optr[(size_t)row * 256 + j * 64 + tx * 4] =
                make_float4(a * inv, bb2 * inv, c * inv, d * inv);
        }
    }
}

// ---------------------------------------------------------------------------
extern "C" void kernel_launch(void* const* d_in, const int* in_sizes, int n_in,
                              void* d_out, int out_size)
{
    const float* x  = (const float*)d_in[0];
    const float* Wf = (const float*)d_in[1];
    const float* bf = (const float*)d_in[2];
    const float* Wg = (const float*)d_in[3];
    const float* bg = (const float*)d_in[4];
    const float* Wh = (const float*)d_in[5];
    const float* bh = (const float*)d_in[6];
    const float* Wv = (const float*)d_in[7];
    const float* bv = (const float*)d_in[8];
    float* out = (float*)d_out;

    k_proj_fg<<<256, 256>>>(x, Wf, bf, Wg, bg);
    k_gemm256<<<dim3(256, 4), 256>>>(x, Wh, bh, nullptr, nullptr, 0);
    k_attn<<<dim3(64, 4), 256>>>();
    k_gemm256<<<dim3(256, 4), 256>>>(nullptr, Wv, bv, x, out, 1);
}